// round 2
// baseline (speedup 1.0000x reference)
#include <cuda_runtime.h>

#define N0 585728
#define N1 22528
#define N2 2048
#define E1 563200
#define E2 20480
#define IN_C 602
#define HID 256
#define OUT_C 41

// -------- scratch (static device globals; no allocation) --------
__device__ __align__(16) float g_agg1[(size_t)N1 * IN_C];   // 54.2 MB
__device__ __align__(16) float g_h[(size_t)N1 * HID];       // 23 MB
__device__ __align__(16) float g_agg2[(size_t)N2 * HID];    // 2 MB
__device__ int g_cnt1[N1];
__device__ int g_off1[N1 + 1];
__device__ int g_cur1[N1];
__device__ int g_bkt1[E1];
__device__ int g_cnt2[N2];
__device__ int g_off2[N2 + 1];
__device__ int g_cur2[N2];
__device__ int g_bkt2[E2];

// ---------------- init ----------------
__global__ void k_zero() {
    int i = blockIdx.x * blockDim.x + threadIdx.x;
    if (i < N1) g_cnt1[i] = 0;
    if (i < N2) g_cnt2[i] = 0;
}

// ---------------- degree count (edge_index is int32: row0=src, row1=dst) ----
__global__ void k_count(const int* __restrict__ ei, int E, int which) {
    int e = blockIdx.x * blockDim.x + threadIdx.x;
    if (e < E) {
        int dst = ei[E + e];
        atomicAdd(which ? &g_cnt2[dst] : &g_cnt1[dst], 1);
    }
}

// ---------------- single-block exclusive scan ----------------
__global__ void k_scan(int which) {
    int* cnt; int* off; int* cur; int n;
    if (which == 0) { cnt = g_cnt1; off = g_off1; cur = g_cur1; n = N1; }
    else            { cnt = g_cnt2; off = g_off2; cur = g_cur2; n = N2; }

    __shared__ int wsum[32];
    __shared__ int s_carry;
    int t = threadIdx.x;          // 1024 threads
    int lane = t & 31, wid = t >> 5;
    if (t == 0) s_carry = 0;
    __syncthreads();

    for (int base = 0; base < n; base += 1024) {
        int i = base + t;
        int v = (i < n) ? cnt[i] : 0;
        int inc = v;
#pragma unroll
        for (int d = 1; d < 32; d <<= 1) {
            int u = __shfl_up_sync(0xffffffffu, inc, d);
            if (lane >= d) inc += u;
        }
        if (lane == 31) wsum[wid] = inc;
        __syncthreads();
        if (wid == 0) {
            int ws = wsum[lane];
            int winc = ws;
#pragma unroll
            for (int d = 1; d < 32; d <<= 1) {
                int u = __shfl_up_sync(0xffffffffu, winc, d);
                if (lane >= d) winc += u;
            }
            wsum[lane] = winc - ws;   // exclusive warp-base
        }
        __syncthreads();
        int excl = inc - v + wsum[wid] + s_carry;
        if (i < n) { off[i] = excl; cur[i] = excl; }
        __syncthreads();              // everyone done reading s_carry/wsum
        if (t == 1023) s_carry = excl + v;
        __syncthreads();
    }
    if (t == 0) off[n] = s_carry;
}

// ---------------- CSR fill ----------------
__global__ void k_fill(const int* __restrict__ ei, int E, int which) {
    int e = blockIdx.x * blockDim.x + threadIdx.x;
    if (e < E) {
        int src = ei[e];
        int dst = ei[E + e];
        int p = atomicAdd(which ? &g_cur2[dst] : &g_cur1[dst], 1);
        (which ? g_bkt2 : g_bkt1)[p] = src;
    }
}

// ---------------- layer-1 mean aggregation (602 feats, float2) ----------------
__global__ void __launch_bounds__(128) k_agg1(const float* __restrict__ x) {
    int dst = blockIdx.x;
    int t = threadIdx.x;                       // 128 threads
    int s = g_off1[dst], e = g_off1[dst + 1];
    float2 acc0 = {0.f, 0.f}, acc1 = {0.f, 0.f}, acc2 = {0.f, 0.f};
    const float2* xb = reinterpret_cast<const float2*>(x);   // 301 float2 per row
    int f2 = t + 256;                                        // only slot 2 is guarded
    int i = s;
    for (; i + 1 < e; i += 2) {
        long long r0 = (long long)g_bkt1[i] * 301;
        long long r1 = (long long)g_bkt1[i + 1] * 301;
        float2 a = __ldg(&xb[r0 + t]);
        float2 b = __ldg(&xb[r0 + t + 128]);
        float2 c = (f2 < 301) ? __ldg(&xb[r0 + f2]) : make_float2(0.f, 0.f);
        float2 d = __ldg(&xb[r1 + t]);
        float2 g = __ldg(&xb[r1 + t + 128]);
        float2 h = (f2 < 301) ? __ldg(&xb[r1 + f2]) : make_float2(0.f, 0.f);
        acc0.x += a.x + d.x; acc0.y += a.y + d.y;
        acc1.x += b.x + g.x; acc1.y += b.y + g.y;
        acc2.x += c.x + h.x; acc2.y += c.y + h.y;
    }
    if (i < e) {
        long long r0 = (long long)g_bkt1[i] * 301;
        float2 a = __ldg(&xb[r0 + t]);
        float2 b = __ldg(&xb[r0 + t + 128]);
        acc0.x += a.x; acc0.y += a.y;
        acc1.x += b.x; acc1.y += b.y;
        if (f2 < 301) { float2 c = __ldg(&xb[r0 + f2]); acc2.x += c.x; acc2.y += c.y; }
    }
    float inv = (e > s) ? 1.0f / (float)(e - s) : 0.0f;
    float2* ob = reinterpret_cast<float2*>(g_agg1) + (long long)dst * 301;
    ob[t]       = make_float2(acc0.x * inv, acc0.y * inv);
    ob[t + 128] = make_float2(acc1.x * inv, acc1.y * inv);
    if (f2 < 301) ob[f2] = make_float2(acc2.x * inv, acc2.y * inv);
}

// ---------------- fused GEMM1: h = relu([agg1 | x_dst] @ [Wl1;Wr1] + bl1) ----------------
// M=22528, logical K=1204, N=256. Tiles: 128x64, BK=16, 256 threads, 8x4 per thread.
__global__ void __launch_bounds__(256) k_gemm1(const float* __restrict__ x,
                                               const float* __restrict__ Wl1,
                                               const float* __restrict__ bl1,
                                               const float* __restrict__ Wr1) {
    __shared__ __align__(16) float As[16][132];   // [k][m], padded
    __shared__ __align__(16) float Bs[16][64];    // [k][n]
    int tid = threadIdx.x;
    int bm = blockIdx.x * 128;
    int bn = blockIdx.y * 64;
    int tx = tid & 15, ty = tid >> 4;

    float acc[8][4];
#pragma unroll
    for (int r = 0; r < 8; r++)
#pragma unroll
        for (int c = 0; c < 4; c++) acc[r][c] = 0.f;

    for (int kk = 0; kk < 1204; kk += 16) {
        // load A tile (128 rows x 16 k)
#pragma unroll
        for (int i = 0; i < 8; i++) {
            int lin = tid + i * 256;
            int ml = lin >> 4, kc = lin & 15;
            int kl = kk + kc;
            long long row = bm + ml;
            float v = 0.f;
            if (kl < 602)       v = g_agg1[row * 602 + kl];
            else if (kl < 1204) v = x[row * 602 + (kl - 602)];
            As[kc][ml] = v;
        }
        // load B tile (16 k x 64 n)
#pragma unroll
        for (int i = 0; i < 4; i++) {
            int lin = tid + i * 256;
            int kc = lin >> 6, col = lin & 63;
            int kl = kk + kc;
            float v = 0.f;
            if (kl < 602)       v = Wl1[(long long)kl * 256 + bn + col];
            else if (kl < 1204) v = Wr1[(long long)(kl - 602) * 256 + bn + col];
            Bs[kc][col] = v;
        }
        __syncthreads();
#pragma unroll
        for (int k = 0; k < 16; k++) {
            float4 a0 = *reinterpret_cast<const float4*>(&As[k][tx * 4]);
            float4 a1 = *reinterpret_cast<const float4*>(&As[k][64 + tx * 4]);
            float4 b  = *reinterpret_cast<const float4*>(&Bs[k][ty * 4]);
            float av[8] = {a0.x, a0.y, a0.z, a0.w, a1.x, a1.y, a1.z, a1.w};
            float bv[4] = {b.x, b.y, b.z, b.w};
#pragma unroll
            for (int r = 0; r < 8; r++)
#pragma unroll
                for (int c = 0; c < 4; c++) acc[r][c] += av[r] * bv[c];
        }
        __syncthreads();
    }

    int n0 = bn + ty * 4;
    float b0 = bl1[n0], b1 = bl1[n0 + 1], b2 = bl1[n0 + 2], b3 = bl1[n0 + 3];
#pragma unroll
    for (int r = 0; r < 8; r++) {
        int row = bm + ((r < 4) ? (tx * 4 + r) : (64 + tx * 4 + r - 4));
        float4 o;
        o.x = fmaxf(acc[r][0] + b0, 0.f);
        o.y = fmaxf(acc[r][1] + b1, 0.f);
        o.z = fmaxf(acc[r][2] + b2, 0.f);
        o.w = fmaxf(acc[r][3] + b3, 0.f);
        *reinterpret_cast<float4*>(&g_h[(long long)row * 256 + n0]) = o;
    }
}

// ---------------- layer-2 mean aggregation (256 feats, float4) ----------------
__global__ void __launch_bounds__(64) k_agg2() {
    int dst = blockIdx.x;
    int t = threadIdx.x;     // 64 threads, one float4 each
    int s = g_off2[dst], e = g_off2[dst + 1];
    float4 acc = {0.f, 0.f, 0.f, 0.f};
    const float4* hb = reinterpret_cast<const float4*>(g_h);
    for (int i = s; i < e; i++) {
        float4 v = __ldg(&hb[(long long)g_bkt2[i] * 64 + t]);
        acc.x += v.x; acc.y += v.y; acc.z += v.z; acc.w += v.w;
    }
    float inv = (e > s) ? 1.0f / (float)(e - s) : 0.0f;
    acc.x *= inv; acc.y *= inv; acc.z *= inv; acc.w *= inv;
    reinterpret_cast<float4*>(g_agg2)[(long long)dst * 64 + t] = acc;
}

// ---------------- GEMM2 + bias + log_softmax ----------------
__global__ void __launch_bounds__(64) k_out(const float* __restrict__ Wl2,
                                            const float* __restrict__ bl2,
                                            const float* __restrict__ Wr2,
                                            float* __restrict__ out) {
    __shared__ __align__(16) float sA[HID];
    __shared__ __align__(16) float sH[HID];
    __shared__ float sO[OUT_C];
    __shared__ float s_mx, s_ls;
    int row = blockIdx.x, t = threadIdx.x;
    reinterpret_cast<float4*>(sA)[t] = reinterpret_cast<const float4*>(g_agg2)[(long long)row * 64 + t];
    reinterpret_cast<float4*>(sH)[t] = reinterpret_cast<const float4*>(g_h)[(long long)row * 64 + t];
    __syncthreads();
    if (t < OUT_C) {
        float acc = bl2[t];
#pragma unroll 8
        for (int k = 0; k < HID; k++)
            acc += sA[k] * __ldg(&Wl2[k * OUT_C + t]) + sH[k] * __ldg(&Wr2[k * OUT_C + t]);
        sO[t] = acc;
    }
    __syncthreads();
    if (t == 0) {
        float mx = -1e30f;
        for (int j = 0; j < OUT_C; j++) mx = fmaxf(mx, sO[j]);
        float se = 0.f;
        for (int j = 0; j < OUT_C; j++) se += expf(sO[j] - mx);
        s_mx = mx; s_ls = logf(se);
    }
    __syncthreads();
    if (t < OUT_C) out[(long long)row * OUT_C + t] = sO[t] - s_mx - s_ls;
}

// ---------------- launch ----------------
extern "C" void kernel_launch(void* const* d_in, const int* in_sizes, int n_in,
                              void* d_out, int out_size) {
    const float* x   = (const float*)d_in[0];
    const int*   ei1 = (const int*)d_in[1];     // int32 [2, E1] (JAX x64 disabled)
    const int*   ei2 = (const int*)d_in[2];     // int32 [2, E2]
    const float* Wl1 = (const float*)d_in[3];
    const float* bl1 = (const float*)d_in[4];
    const float* Wr1 = (const float*)d_in[5];
    const float* Wl2 = (const float*)d_in[6];
    const float* bl2 = (const float*)d_in[7];
    const float* Wr2 = (const float*)d_in[8];
    float* out = (float*)d_out;

    k_zero<<<(N1 + 255) / 256, 256>>>();
    k_count<<<(E1 + 255) / 256, 256>>>(ei1, E1, 0);
    k_count<<<(E2 + 255) / 256, 256>>>(ei2, E2, 1);
    k_scan<<<1, 1024>>>(0);
    k_scan<<<1, 1024>>>(1);
    k_fill<<<(E1 + 255) / 256, 256>>>(ei1, E1, 0);
    k_fill<<<(E2 + 255) / 256, 256>>>(ei2, E2, 1);
    k_agg1<<<N1, 128>>>(x);
    k_gemm1<<<dim3(176, 4), 256>>>(x, Wl1, bl1, Wr1);
    k_agg2<<<N2, 64>>>();
    k_out<<<N2, 64>>>(Wl2, bl2, Wr2, out);
}

// round 3
// speedup vs baseline: 1.0997x; 1.0997x over previous
#include <cuda_runtime.h>
#include <cstdint>

#define N0 585728
#define N1 22528
#define N2 2048
#define E1 563200
#define E2 20480
#define IN_C 602
#define HID 256
#define OUT_C 41

// -------- scratch (static device globals; no allocation) --------
__device__ __align__(16) float g_agg1[(size_t)N1 * IN_C];   // 54.2 MB
__device__ __align__(16) float g_h[(size_t)N1 * HID];       // 23 MB
__device__ __align__(16) float g_agg2[(size_t)N2 * HID];    // 2 MB
__device__ int g_cnt1[N1];
__device__ int g_off1[N1 + 1];
__device__ int g_cur1[N1];
__device__ int g_bkt1[E1];
__device__ int g_cnt2[N2];
__device__ int g_off2[N2 + 1];
__device__ int g_cur2[N2];
__device__ int g_bkt2[E2];

// ---------------- init ----------------
__global__ void k_zero() {
    int i = blockIdx.x * blockDim.x + threadIdx.x;
    if (i < N1) g_cnt1[i] = 0;
    if (i < N2) g_cnt2[i] = 0;
}

// ---------------- degree count (edge_index int32: row0=src, row1=dst) -------
__global__ void k_count(const int* __restrict__ ei, int E, int which) {
    int e = blockIdx.x * blockDim.x + threadIdx.x;
    if (e < E) {
        int dst = ei[E + e];
        atomicAdd(which ? &g_cnt2[dst] : &g_cnt1[dst], 1);
    }
}

// ---------------- single-pass chunked exclusive scan (both layers, 2 blocks) -
__global__ void __launch_bounds__(1024) k_scan2() {
    int which = blockIdx.x;
    int* cnt; int* off; int* cur; int n;
    if (which == 0) { cnt = g_cnt1; off = g_off1; cur = g_cur1; n = N1; }
    else            { cnt = g_cnt2; off = g_off2; cur = g_cur2; n = N2; }
    const int C = (n + 1023) / 1024;      // 22 or 2
    int t = threadIdx.x, lane = t & 31, wid = t >> 5;

    int v[32];
    int base_i = t * C;
    int total = 0;
#pragma unroll 4
    for (int j = 0; j < C; j++) {
        int i = base_i + j;
        int val = (i < n) ? cnt[i] : 0;
        v[j] = total;          // exclusive local prefix
        total += val;
    }
    // block exclusive scan of per-thread totals
    int inc = total;
#pragma unroll
    for (int d = 1; d < 32; d <<= 1) {
        int u = __shfl_up_sync(0xffffffffu, inc, d);
        if (lane >= d) inc += u;
    }
    __shared__ int wsum[32];
    if (lane == 31) wsum[wid] = inc;
    __syncthreads();
    if (wid == 0) {
        int ws = wsum[lane];
        int winc = ws;
#pragma unroll
        for (int d = 1; d < 32; d <<= 1) {
            int u = __shfl_up_sync(0xffffffffu, winc, d);
            if (lane >= d) winc += u;
        }
        wsum[lane] = winc - ws;   // exclusive warp base
    }
    __syncthreads();
    int base = inc - total + wsum[wid];
#pragma unroll 4
    for (int j = 0; j < C; j++) {
        int i = base_i + j;
        if (i < n) { int o = base + v[j]; off[i] = o; cur[i] = o; }
    }
    if (t == 1023) off[n] = base + total;
}

// ---------------- CSR fill ----------------
__global__ void k_fill(const int* __restrict__ ei, int E, int which) {
    int e = blockIdx.x * blockDim.x + threadIdx.x;
    if (e < E) {
        int src = ei[e];
        int dst = ei[E + e];
        int p = atomicAdd(which ? &g_cur2[dst] : &g_cur1[dst], 1);
        (which ? g_bkt2 : g_bkt1)[p] = src;
    }
}

// ---------------- layer-1 mean aggregation (602 feats, float2) --------------
__global__ void __launch_bounds__(128) k_agg1(const float* __restrict__ x) {
    int dst = blockIdx.x;
    int t = threadIdx.x;                       // 128 threads
    int s = g_off1[dst], e = g_off1[dst + 1];
    float2 acc0 = {0.f, 0.f}, acc1 = {0.f, 0.f}, acc2 = {0.f, 0.f};
    const float2* xb = reinterpret_cast<const float2*>(x);   // 301 float2/row
    int f2 = t + 256;
    int i = s;
    for (; i + 1 < e; i += 2) {
        long long r0 = (long long)g_bkt1[i] * 301;
        long long r1 = (long long)g_bkt1[i + 1] * 301;
        float2 a = __ldg(&xb[r0 + t]);
        float2 b = __ldg(&xb[r0 + t + 128]);
        float2 c = (f2 < 301) ? __ldg(&xb[r0 + f2]) : make_float2(0.f, 0.f);
        float2 d = __ldg(&xb[r1 + t]);
        float2 g = __ldg(&xb[r1 + t + 128]);
        float2 h = (f2 < 301) ? __ldg(&xb[r1 + f2]) : make_float2(0.f, 0.f);
        acc0.x += a.x + d.x; acc0.y += a.y + d.y;
        acc1.x += b.x + g.x; acc1.y += b.y + g.y;
        acc2.x += c.x + h.x; acc2.y += c.y + h.y;
    }
    if (i < e) {
        long long r0 = (long long)g_bkt1[i] * 301;
        float2 a = __ldg(&xb[r0 + t]);
        float2 b = __ldg(&xb[r0 + t + 128]);
        acc0.x += a.x; acc0.y += a.y;
        acc1.x += b.x; acc1.y += b.y;
        if (f2 < 301) { float2 c = __ldg(&xb[r0 + f2]); acc2.x += c.x; acc2.y += c.y; }
    }
    float inv = (e > s) ? 1.0f / (float)(e - s) : 0.0f;
    float2* ob = reinterpret_cast<float2*>(g_agg1) + (long long)dst * 301;
    ob[t]       = make_float2(acc0.x * inv, acc0.y * inv);
    ob[t + 128] = make_float2(acc1.x * inv, acc1.y * inv);
    if (f2 < 301) ob[f2] = make_float2(acc2.x * inv, acc2.y * inv);
}

// ---------------- tf32 helpers ----------------
__device__ __forceinline__ unsigned f2tf32(float v) {
    unsigned u;
    asm("cvt.rna.tf32.f32 %0, %1;" : "=r"(u) : "f"(v));
    return u;
}
__device__ __forceinline__ void mma_tf32(float& c0, float& c1, float& c2, float& c3,
                                         unsigned a0, unsigned a1, unsigned a2, unsigned a3,
                                         unsigned b0, unsigned b1) {
    asm volatile("mma.sync.aligned.m16n8k8.row.col.f32.tf32.tf32.f32 "
                 "{%0,%1,%2,%3}, {%4,%5,%6,%7}, {%8,%9}, {%0,%1,%2,%3};"
                 : "+f"(c0), "+f"(c1), "+f"(c2), "+f"(c3)
                 : "r"(a0), "r"(a1), "r"(a2), "r"(a3), "r"(b0), "r"(b1));
}

// ---------------- fused GEMM1 (tf32 tensor cores) ---------------------------
// h = relu([agg1 | x_dst] @ [Wl1;Wr1] + bl1)
// M=22528, K=1204, N=256. Block 128x64, 8 warps (4x2), warp 32x32, BK=16.
__global__ void __launch_bounds__(256) k_gemm1(const float* __restrict__ x,
                                               const float* __restrict__ Wl1,
                                               const float* __restrict__ bl1,
                                               const float* __restrict__ Wr1) {
    __shared__ __align__(16) unsigned As[16][132];   // [k][m] tf32 bits
    __shared__ __align__(16) unsigned Bs[16][68];    // [k][n] tf32 bits
    int tid = threadIdx.x;
    int bm = blockIdx.x * 128;
    int bn = blockIdx.y * 64;
    int warp = tid >> 5, lane = tid & 31;
    int wm = (warp & 3) * 32;          // warp M offset in tile
    int wn = (warp >> 2) * 32;         // warp N offset in tile
    int gid = lane >> 2, tig = lane & 3;

    float acc[2][4][4];
#pragma unroll
    for (int mt = 0; mt < 2; mt++)
#pragma unroll
        for (int nt = 0; nt < 4; nt++)
#pragma unroll
            for (int r = 0; r < 4; r++) acc[mt][nt][r] = 0.f;

    for (int kk = 0; kk < 1216; kk += 16) {
        // A tile: 128 rows x 16 k (8 elems/thread)
#pragma unroll
        for (int i = 0; i < 8; i++) {
            int lin = tid + i * 256;
            int ml = lin >> 4, kc = lin & 15;
            int kl = kk + kc;
            long long row = bm + ml;
            float v = 0.f;
            if (kl < 602)       v = g_agg1[row * 602 + kl];
            else if (kl < 1204) v = x[row * 602 + (kl - 602)];
            As[kc][ml] = f2tf32(v);
        }
        // B tile: 16 k x 64 n (4 elems/thread)
#pragma unroll
        for (int i = 0; i < 4; i++) {
            int lin = tid + i * 256;
            int kc = lin >> 6, col = lin & 63;
            int kl = kk + kc;
            float v = 0.f;
            if (kl < 602)       v = Wl1[(long long)kl * 256 + bn + col];
            else if (kl < 1204) v = Wr1[(long long)(kl - 602) * 256 + bn + col];
            Bs[kc][col] = f2tf32(v);
        }
        __syncthreads();
#pragma unroll
        for (int ks = 0; ks < 16; ks += 8) {
            unsigned af[2][4], bf[4][2];
#pragma unroll
            for (int mt = 0; mt < 2; mt++) {
                int m0 = wm + mt * 16;
                af[mt][0] = As[ks + tig][m0 + gid];
                af[mt][1] = As[ks + tig][m0 + gid + 8];
                af[mt][2] = As[ks + tig + 4][m0 + gid];
                af[mt][3] = As[ks + tig + 4][m0 + gid + 8];
            }
#pragma unroll
            for (int nt = 0; nt < 4; nt++) {
                int n0 = wn + nt * 8;
                bf[nt][0] = Bs[ks + tig][n0 + gid];
                bf[nt][1] = Bs[ks + tig + 4][n0 + gid];
            }
#pragma unroll
            for (int mt = 0; mt < 2; mt++)
#pragma unroll
                for (int nt = 0; nt < 4; nt++)
                    mma_tf32(acc[mt][nt][0], acc[mt][nt][1], acc[mt][nt][2], acc[mt][nt][3],
                             af[mt][0], af[mt][1], af[mt][2], af[mt][3],
                             bf[nt][0], bf[nt][1]);
        }
        __syncthreads();
    }

    // epilogue: bias + relu, float2 stores (cols tig*2, tig*2+1 per n-tile)
#pragma unroll
    for (int nt = 0; nt < 4; nt++) {
        int c = bn + wn + nt * 8 + tig * 2;
        float b0 = bl1[c], b1 = bl1[c + 1];
#pragma unroll
        for (int mt = 0; mt < 2; mt++) {
            int r0 = bm + wm + mt * 16 + gid;
            float2 o0, o1;
            o0.x = fmaxf(acc[mt][nt][0] + b0, 0.f);
            o0.y = fmaxf(acc[mt][nt][1] + b1, 0.f);
            o1.x = fmaxf(acc[mt][nt][2] + b0, 0.f);
            o1.y = fmaxf(acc[mt][nt][3] + b1, 0.f);
            *reinterpret_cast<float2*>(&g_h[(long long)r0 * 256 + c]) = o0;
            *reinterpret_cast<float2*>(&g_h[(long long)(r0 + 8) * 256 + c]) = o1;
        }
    }
}

// ---------------- layer-2 mean aggregation (256 feats, float4) --------------
__global__ void __launch_bounds__(64) k_agg2() {
    int dst = blockIdx.x;
    int t = threadIdx.x;
    int s = g_off2[dst], e = g_off2[dst + 1];
    float4 acc = {0.f, 0.f, 0.f, 0.f};
    const float4* hb = reinterpret_cast<const float4*>(g_h);
    for (int i = s; i < e; i++) {
        float4 v = __ldg(&hb[(long long)g_bkt2[i] * 64 + t]);
        acc.x += v.x; acc.y += v.y; acc.z += v.z; acc.w += v.w;
    }
    float inv = (e > s) ? 1.0f / (float)(e - s) : 0.0f;
    acc.x *= inv; acc.y *= inv; acc.z *= inv; acc.w *= inv;
    reinterpret_cast<float4*>(g_agg2)[(long long)dst * 64 + t] = acc;
}

// ---------------- GEMM2 + bias + log_softmax ----------------
__global__ void __launch_bounds__(64) k_out(const float* __restrict__ Wl2,
                                            const float* __restrict__ bl2,
                                            const float* __restrict__ Wr2,
                                            float* __restrict__ out) {
    __shared__ __align__(16) float sA[HID];
    __shared__ __align__(16) float sH[HID];
    __shared__ float sO[OUT_C];
    __shared__ float s_mx, s_ls;
    int row = blockIdx.x, t = threadIdx.x;
    reinterpret_cast<float4*>(sA)[t] = reinterpret_cast<const float4*>(g_agg2)[(long long)row * 64 + t];
    reinterpret_cast<float4*>(sH)[t] = reinterpret_cast<const float4*>(g_h)[(long long)row * 64 + t];
    __syncthreads();
    if (t < OUT_C) {
        float acc = bl2[t];
#pragma unroll 8
        for (int k = 0; k < HID; k++)
            acc += sA[k] * __ldg(&Wl2[k * OUT_C + t]) + sH[k] * __ldg(&Wr2[k * OUT_C + t]);
        sO[t] = acc;
    }
    __syncthreads();
    if (t == 0) {
        float mx = -1e30f;
        for (int j = 0; j < OUT_C; j++) mx = fmaxf(mx, sO[j]);
        float se = 0.f;
        for (int j = 0; j < OUT_C; j++) se += expf(sO[j] - mx);
        s_mx = mx; s_ls = logf(se);
    }
    __syncthreads();
    if (t < OUT_C) out[(long long)row * OUT_C + t] = sO[t] - s_mx - s_ls;
}

// ---------------- launch ----------------
extern "C" void kernel_launch(void* const* d_in, const int* in_sizes, int n_in,
                              void* d_out, int out_size) {
    const float* x   = (const float*)d_in[0];
    const int*   ei1 = (const int*)d_in[1];     // int32 [2, E1]
    const int*   ei2 = (const int*)d_in[2];     // int32 [2, E2]
    const float* Wl1 = (const float*)d_in[3];
    const float* bl1 = (const float*)d_in[4];
    const float* Wr1 = (const float*)d_in[5];
    const float* Wl2 = (const float*)d_in[6];
    const float* bl2 = (const float*)d_in[7];
    const float* Wr2 = (const float*)d_in[8];
    float* out = (float*)d_out;

    k_zero<<<(N1 + 255) / 256, 256>>>();
    k_count<<<(E1 + 255) / 256, 256>>>(ei1, E1, 0);
    k_count<<<(E2 + 255) / 256, 256>>>(ei2, E2, 1);
    k_scan2<<<2, 1024>>>();
    k_fill<<<(E1 + 255) / 256, 256>>>(ei1, E1, 0);
    k_fill<<<(E2 + 255) / 256, 256>>>(ei2, E2, 1);
    k_agg1<<<N1, 128>>>(x);
    k_gemm1<<<dim3(176, 4), 256>>>(x, Wl1, bl1, Wr1);
    k_agg2<<<N2, 64>>>();
    k_out<<<N2, 64>>>(Wl2, bl2, Wr2, out);
}

// round 4
// speedup vs baseline: 3.0217x; 2.7478x over previous
#include <cuda_runtime.h>
#include <cuda_bf16.h>
#include <cstdint>

#define N0 585728
#define N1 22528
#define N2 2048
#define E1 563200
#define E2 20480
#define IN_C 602
#define HID 256
#define OUT_C 41
#define KP 608           // padded half-K (602 -> 608)
#define KTOT 1216        // 2*KP
#define NKT 38           // KTOT/32 k-tiles

// -------- scratch (static device globals; no allocation) --------
__device__ __align__(16) __nv_bfloat162 g_a1b[(size_t)N1 * (KP / 2)];  // agg1 bf16 [N1][608]
__device__ __align__(16) __nv_bfloat162 g_xb[(size_t)N1 * (KP / 2)];   // x_dst bf16 [N1][608]
__device__ __align__(16) __nv_bfloat16 g_wbT[(size_t)HID * KTOT];      // W^T bf16 [256][1216]
__device__ __align__(16) float g_h[(size_t)N1 * HID];                  // 23 MB
__device__ __align__(16) float g_agg2[(size_t)N2 * HID];
__device__ int g_cnt1[N1];
__device__ int g_off1[N1 + 1];
__device__ int g_cur1[N1];
__device__ int g_bkt1[E1];
__device__ int g_cnt2[N2];
__device__ int g_off2[N2 + 1];
__device__ int g_cur2[N2];
__device__ int g_bkt2[E2];

// ---------------- init ----------------
__global__ void k_zero() {
    int i = blockIdx.x * blockDim.x + threadIdx.x;
    if (i < N1) g_cnt1[i] = 0;
    if (i < N2) g_cnt2[i] = 0;
}

// ---------------- degree count (both layers, one launch) --------------------
__global__ void k_count_all(const int* __restrict__ ei1, const int* __restrict__ ei2) {
    int e = blockIdx.x * blockDim.x + threadIdx.x;
    if (e < E1) {
        atomicAdd(&g_cnt1[ei1[E1 + e]], 1);
    } else if (e < E1 + E2) {
        int f = e - E1;
        atomicAdd(&g_cnt2[ei2[E2 + f]], 1);
    }
}

// ---------------- chunked exclusive scan (constexpr chunk -> registers) -----
template <int C, int NN>
__device__ __forceinline__ void scan_impl(const int* __restrict__ cnt,
                                          int* __restrict__ off,
                                          int* __restrict__ cur) {
    int t = threadIdx.x, lane = t & 31, wid = t >> 5;
    int v[C];
    int base_i = t * C;
    int total = 0;
#pragma unroll
    for (int j = 0; j < C; j++) {
        int i = base_i + j;
        int val = (i < NN) ? cnt[i] : 0;
        v[j] = total;
        total += val;
    }
    int inc = total;
#pragma unroll
    for (int d = 1; d < 32; d <<= 1) {
        int u = __shfl_up_sync(0xffffffffu, inc, d);
        if (lane >= d) inc += u;
    }
    __shared__ int wsum[32];
    if (lane == 31) wsum[wid] = inc;
    __syncthreads();
    if (wid == 0) {
        int ws = wsum[lane];
        int winc = ws;
#pragma unroll
        for (int d = 1; d < 32; d <<= 1) {
            int u = __shfl_up_sync(0xffffffffu, winc, d);
            if (lane >= d) winc += u;
        }
        wsum[lane] = winc - ws;
    }
    __syncthreads();
    int base = inc - total + wsum[wid];
#pragma unroll
    for (int j = 0; j < C; j++) {
        int i = base_i + j;
        if (i < NN) { int o = base + v[j]; off[i] = o; cur[i] = o; }
    }
    if (t == 1023) off[NN] = base + total;
}

__global__ void __launch_bounds__(1024) k_scan2() {
    if (blockIdx.x == 0) scan_impl<22, N1>(g_cnt1, g_off1, g_cur1);
    else                 scan_impl<2, N2>(g_cnt2, g_off2, g_cur2);
}

// ---------------- CSR fill (both layers) ----------------
__global__ void k_fill_all(const int* __restrict__ ei1, const int* __restrict__ ei2) {
    int e = blockIdx.x * blockDim.x + threadIdx.x;
    if (e < E1) {
        int p = atomicAdd(&g_cur1[ei1[E1 + e]], 1);
        g_bkt1[p] = ei1[e];
    } else if (e < E1 + E2) {
        int f = e - E1;
        int p = atomicAdd(&g_cur2[ei2[E2 + f]], 1);
        g_bkt2[p] = ei2[f];
    }
}

// ---------------- weight prep: g_wbT[n][k] bf16, concat+pad -----------------
__global__ void k_prep(const float* __restrict__ Wl1, const float* __restrict__ Wr1) {
    int idx = blockIdx.x * blockDim.x + threadIdx.x;   // k*256+n
    if (idx >= KTOT * HID) return;
    int k = idx >> 8, n = idx & 255;
    float v = 0.f;
    if (k < IN_C)                      v = Wl1[(size_t)k * HID + n];
    else if (k >= KP && k < KP + IN_C) v = Wr1[(size_t)(k - KP) * HID + n];
    g_wbT[(size_t)n * KTOT + k] = __float2bfloat16(v);
}

// ---------------- x_dst -> bf16 padded ----------------
__global__ void k_xcast(const float* __restrict__ x) {
    int idx = blockIdx.x * blockDim.x + threadIdx.x;   // word index, [N1*304]
    if (idx >= N1 * (KP / 2)) return;
    int row = idx / (KP / 2), w = idx % (KP / 2);
    int c = w * 2;
    float a = (c < IN_C)     ? x[(size_t)row * IN_C + c] : 0.f;
    float b = (c + 1 < IN_C) ? x[(size_t)row * IN_C + c + 1] : 0.f;
    g_xb[idx] = __floats2bfloat162_rn(a, b);
}

// ---------------- layer-1 mean aggregation -> bf16 padded -------------------
__global__ void __launch_bounds__(128) k_agg1(const float* __restrict__ x) {
    int dst = blockIdx.x;
    int t = threadIdx.x;                       // 128 threads
    int s = g_off1[dst], e = g_off1[dst + 1];
    float2 acc0 = {0.f, 0.f}, acc1 = {0.f, 0.f}, acc2 = {0.f, 0.f};
    const float2* xb = reinterpret_cast<const float2*>(x);   // 301 float2/row
    int f2 = t + 256;
    int i = s;
    for (; i + 1 < e; i += 2) {
        long long r0 = (long long)g_bkt1[i] * 301;
        long long r1 = (long long)g_bkt1[i + 1] * 301;
        float2 a = __ldg(&xb[r0 + t]);
        float2 b = __ldg(&xb[r0 + t + 128]);
        float2 c = (f2 < 301) ? __ldg(&xb[r0 + f2]) : make_float2(0.f, 0.f);
        float2 d = __ldg(&xb[r1 + t]);
        float2 g = __ldg(&xb[r1 + t + 128]);
        float2 h = (f2 < 301) ? __ldg(&xb[r1 + f2]) : make_float2(0.f, 0.f);
        acc0.x += a.x + d.x; acc0.y += a.y + d.y;
        acc1.x += b.x + g.x; acc1.y += b.y + g.y;
        acc2.x += c.x + h.x; acc2.y += c.y + h.y;
    }
    if (i < e) {
        long long r0 = (long long)g_bkt1[i] * 301;
        float2 a = __ldg(&xb[r0 + t]);
        float2 b = __ldg(&xb[r0 + t + 128]);
        acc0.x += a.x; acc0.y += a.y;
        acc1.x += b.x; acc1.y += b.y;
        if (f2 < 301) { float2 c = __ldg(&xb[r0 + f2]); acc2.x += c.x; acc2.y += c.y; }
    }
    float inv = (e > s) ? 1.0f / (float)(e - s) : 0.0f;
    __nv_bfloat162* ob = g_a1b + (long long)dst * (KP / 2);    // 304 words/row
    ob[t]       = __floats2bfloat162_rn(acc0.x * inv, acc0.y * inv);
    ob[t + 128] = __floats2bfloat162_rn(acc1.x * inv, acc1.y * inv);
    if (t < 48) {
        int w2 = t + 256;
        __nv_bfloat162 z = __floats2bfloat162_rn(
            (w2 < 301) ? acc2.x * inv : 0.f,
            (w2 < 301) ? acc2.y * inv : 0.f);
        ob[w2] = z;
    }
}

// ---------------- bf16 MMA helpers ----------------
__device__ __forceinline__ void mma_bf16(float& c0, float& c1, float& c2, float& c3,
                                         unsigned a0, unsigned a1, unsigned a2, unsigned a3,
                                         unsigned b0, unsigned b1) {
    asm volatile("mma.sync.aligned.m16n8k16.row.col.f32.bf16.bf16.f32 "
                 "{%0,%1,%2,%3}, {%4,%5,%6,%7}, {%8,%9}, {%0,%1,%2,%3};"
                 : "+f"(c0), "+f"(c1), "+f"(c2), "+f"(c3)
                 : "r"(a0), "r"(a1), "r"(a2), "r"(a3), "r"(b0), "r"(b1));
}
__device__ __forceinline__ void cpa16(unsigned saddr, const void* g) {
    asm volatile("cp.async.cg.shared.global [%0], [%1], 16;" :: "r"(saddr), "l"(g));
}
__device__ __forceinline__ void cpa_commit() { asm volatile("cp.async.commit_group;"); }

// ---------------- fused GEMM1 (bf16 tensor cores, cp.async 2-stage) ---------
// h = relu([agg1 | x_dst] @ [Wl1;Wr1] + bl1)
// M=22528, K=1216 (padded), N=256. Block 128x64, 8 warps (4m x 2n), warp 32x32.
// Smem rows padded to 20 words -> frag LDS banks gid*20+tig hit all 32 banks.
#define KSW 20
__global__ void __launch_bounds__(256) k_gemm1(const float* __restrict__ bl1) {
    __shared__ __align__(16) unsigned As[2][128 * KSW];
    __shared__ __align__(16) unsigned Bs[2][64 * KSW];
    int tid = threadIdx.x;
    int bm = blockIdx.x * 128;
    int bn = blockIdx.y * 64;
    int warp = tid >> 5, lane = tid & 31;
    int wm = (warp & 3) * 32;
    int wn = (warp >> 2) * 32;
    int gid = lane >> 2, tig = lane & 3;

    // per-thread load coords
    int ar = tid >> 1;                 // A row (2 chunks/thread)
    int ac = (tid & 1) * 2;            // first chunk (of 4 16B chunks per row)
    int br = tid >> 2;                 // B row (n), 1 chunk/thread
    int bc = tid & 3;

    const __nv_bfloat16* a1p = reinterpret_cast<const __nv_bfloat16*>(g_a1b);
    const __nv_bfloat16* xbp = reinterpret_cast<const __nv_bfloat16*>(g_xb);

    float acc[2][4][4];
#pragma unroll
    for (int mt = 0; mt < 2; mt++)
#pragma unroll
        for (int nt = 0; nt < 4; nt++)
#pragma unroll
            for (int r = 0; r < 4; r++) acc[mt][nt][r] = 0.f;

    unsigned sA[2], sB[2];
    sA[0] = (unsigned)__cvta_generic_to_shared(&As[0][0]);
    sA[1] = (unsigned)__cvta_generic_to_shared(&As[1][0]);
    sB[0] = (unsigned)__cvta_generic_to_shared(&Bs[0][0]);
    sB[1] = (unsigned)__cvta_generic_to_shared(&Bs[1][0]);

    auto load_tile = [&](int buf, int kt) {
        const __nv_bfloat16* src = (kt < 19) ? a1p : xbp;
        int k0 = ((kt < 19) ? kt : kt - 19) * 32;
        // A: 128 rows x 32 bf16
#pragma unroll
        for (int i = 0; i < 2; i++) {
            int c = ac + i;
            const void* g = src + ((size_t)(bm + ar)) * KP + k0 + c * 8;
            cpa16(sA[buf] + (ar * KSW + c * 4) * 4, g);
        }
        // B: 64 n-rows x 32 bf16 from g_wbT
        {
            const void* g = g_wbT + ((size_t)(bn + br)) * KTOT + kt * 32 + bc * 8;
            cpa16(sB[buf] + (br * KSW + bc * 4) * 4, g);
        }
    };

    load_tile(0, 0);
    cpa_commit();

    for (int kt = 0; kt < NKT; kt++) {
        int buf = kt & 1;
        if (kt + 1 < NKT) load_tile(buf ^ 1, kt + 1);
        cpa_commit();
        asm volatile("cp.async.wait_group 1;");
        __syncthreads();

        const unsigned* A = &As[buf][0];
        const unsigned* B = &Bs[buf][0];
#pragma unroll
        for (int half = 0; half < 2; half++) {
            int hb = half * 8;
            unsigned af[2][4], bf[4][2];
#pragma unroll
            for (int mt = 0; mt < 2; mt++) {
                int m0 = wm + mt * 16;
                af[mt][0] = A[(m0 + gid) * KSW + hb + tig];
                af[mt][1] = A[(m0 + gid + 8) * KSW + hb + tig];
                af[mt][2] = A[(m0 + gid) * KSW + hb + tig + 4];
                af[mt][3] = A[(m0 + gid + 8) * KSW + hb + tig + 4];
            }
#pragma unroll
            for (int nt = 0; nt < 4; nt++) {
                int n0 = wn + nt * 8;
                bf[nt][0] = B[(n0 + gid) * KSW + hb + tig];
                bf[nt][1] = B[(n0 + gid) * KSW + hb + tig + 4];
            }
#pragma unroll
            for (int mt = 0; mt < 2; mt++)
#pragma unroll
                for (int nt = 0; nt < 4; nt++)
                    mma_bf16(acc[mt][nt][0], acc[mt][nt][1], acc[mt][nt][2], acc[mt][nt][3],
                             af[mt][0], af[mt][1], af[mt][2], af[mt][3],
                             bf[nt][0], bf[nt][1]);
        }
        __syncthreads();
    }

    // epilogue: bias + relu
#pragma unroll
    for (int nt = 0; nt < 4; nt++) {
        int c = bn + wn + nt * 8 + tig * 2;
        float b0 = bl1[c], b1 = bl1[c + 1];
#pragma unroll
        for (int mt = 0; mt < 2; mt++) {
            int r0 = bm + wm + mt * 16 + gid;
            float2 o0, o1;
            o0.x = fmaxf(acc[mt][nt][0] + b0, 0.f);
            o0.y = fmaxf(acc[mt][nt][1] + b1, 0.f);
            o1.x = fmaxf(acc[mt][nt][2] + b0, 0.f);
            o1.y = fmaxf(acc[mt][nt][3] + b1, 0.f);
            *reinterpret_cast<float2*>(&g_h[(long long)r0 * 256 + c]) = o0;
            *reinterpret_cast<float2*>(&g_h[(long long)(r0 + 8) * 256 + c]) = o1;
        }
    }
}

// ---------------- layer-2 mean aggregation (256 feats, float4) --------------
__global__ void __launch_bounds__(64) k_agg2() {
    int dst = blockIdx.x;
    int t = threadIdx.x;
    int s = g_off2[dst], e = g_off2[dst + 1];
    float4 acc = {0.f, 0.f, 0.f, 0.f};
    const float4* hb = reinterpret_cast<const float4*>(g_h);
    for (int i = s; i < e; i++) {
        float4 v = __ldg(&hb[(long long)g_bkt2[i] * 64 + t]);
        acc.x += v.x; acc.y += v.y; acc.z += v.z; acc.w += v.w;
    }
    float inv = (e > s) ? 1.0f / (float)(e - s) : 0.0f;
    acc.x *= inv; acc.y *= inv; acc.z *= inv; acc.w *= inv;
    reinterpret_cast<float4*>(g_agg2)[(long long)dst * 64 + t] = acc;
}

// ---------------- GEMM2 + bias + log_softmax ----------------
__global__ void __launch_bounds__(64) k_out(const float* __restrict__ Wl2,
                                            const float* __restrict__ bl2,
                                            const float* __restrict__ Wr2,
                                            float* __restrict__ out) {
    __shared__ __align__(16) float sA[HID];
    __shared__ __align__(16) float sH[HID];
    __shared__ float sO[OUT_C];
    __shared__ float s_mx, s_ls;
    int row = blockIdx.x, t = threadIdx.x;
    reinterpret_cast<float4*>(sA)[t] = reinterpret_cast<const float4*>(g_agg2)[(long long)row * 64 + t];
    reinterpret_cast<float4*>(sH)[t] = reinterpret_cast<const float4*>(g_h)[(long long)row * 64 + t];
    __syncthreads();
    if (t < OUT_C) {
        float acc = bl2[t];
#pragma unroll 8
        for (int k = 0; k < HID; k++)
            acc += sA[k] * __ldg(&Wl2[k * OUT_C + t]) + sH[k] * __ldg(&Wr2[k * OUT_C + t]);
        sO[t] = acc;
    }
    __syncthreads();
    if (t == 0) {
        float mx = -1e30f;
        for (int j = 0; j < OUT_C; j++) mx = fmaxf(mx, sO[j]);
        float se = 0.f;
        for (int j = 0; j < OUT_C; j++) se += expf(sO[j] - mx);
        s_mx = mx; s_ls = logf(se);
    }
    __syncthreads();
    if (t < OUT_C) out[(long long)row * OUT_C + t] = sO[t] - s_mx - s_ls;
}

// ---------------- launch ----------------
extern "C" void kernel_launch(void* const* d_in, const int* in_sizes, int n_in,
                              void* d_out, int out_size) {
    const float* x   = (const float*)d_in[0];
    const int*   ei1 = (const int*)d_in[1];     // int32 [2, E1]
    const int*   ei2 = (const int*)d_in[2];     // int32 [2, E2]
    const float* Wl1 = (const float*)d_in[3];
    const float* bl1 = (const float*)d_in[4];
    const float* Wr1 = (const float*)d_in[5];
    const float* Wl2 = (const float*)d_in[6];
    const float* bl2 = (const float*)d_in[7];
    const float* Wr2 = (const float*)d_in[8];
    float* out = (float*)d_out;

    k_zero<<<(N1 + 255) / 256, 256>>>();
    k_count_all<<<(E1 + E2 + 255) / 256, 256>>>(ei1, ei2);
    k_scan2<<<2, 1024>>>();
    k_fill_all<<<(E1 + E2 + 255) / 256, 256>>>(ei1, ei2);
    k_prep<<<(KTOT * HID + 255) / 256, 256>>>(Wl1, Wr1);
    k_xcast<<<(N1 * (KP / 2) + 255) / 256, 256>>>(x);
    k_agg1<<<N1, 128>>>(x);
    k_gemm1<<<dim3(176, 4), 256>>>(bl1);
    k_agg2<<<N2, 64>>>();
    k_out<<<N2, 64>>>(Wl2, bl2, Wr2, out);
}

// round 5
// speedup vs baseline: 3.2276x; 1.0682x over previous
#include <cuda_runtime.h>
#include <cuda_bf16.h>
#include <cstdint>

#define N0 585728
#define N1 22528
#define N2 2048
#define E1 563200
#define E2 20480
#define IN_C 602
#define HID 256
#define OUT_C 41
#define KP 608           // padded half-K (602 -> 608)
#define KTOT 1216        // 2*KP
#define NKT 38           // KTOT/32 k-tiles
#define CAP1 96          // bucket capacity layer1 (Poisson λ=25, >8σ)
#define CAP2 64          // layer2 (λ=10)

// -------- scratch (static device globals; no allocation) --------
__device__ __align__(16) __nv_bfloat162 g_a1b[(size_t)N1 * (KP / 2)];  // agg1 bf16 [N1][608]
__device__ __align__(16) __nv_bfloat162 g_xb[(size_t)N1 * (KP / 2)];   // x_dst bf16 [N1][608]
__device__ __align__(16) __nv_bfloat16 g_wbT[(size_t)HID * KTOT];      // W^T bf16 [256][1216]
__device__ __align__(16) float g_h[(size_t)N1 * HID];
__device__ __align__(16) float g_agg2[(size_t)N2 * HID];
__device__ int g_cnt1[N1];
__device__ int g_bkt1[(size_t)N1 * CAP1];
__device__ int g_cnt2[N2];
__device__ int g_bkt2[(size_t)N2 * CAP2];

// ---------------- zero counters ----------------
__global__ void k_zero_cnt() {
    int i = blockIdx.x * blockDim.x + threadIdx.x;
    if (i < N1) g_cnt1[i] = 0;
    if (i < N2) g_cnt2[i] = 0;
}

// ---------------- bucket fill (both layers, one launch) ---------------------
__global__ void k_fill_all(const int* __restrict__ ei1, const int* __restrict__ ei2) {
    int e = blockIdx.x * blockDim.x + threadIdx.x;
    if (e < E1) {
        int dst = ei1[E1 + e];
        int p = atomicAdd(&g_cnt1[dst], 1);
        if (p < CAP1) g_bkt1[(size_t)dst * CAP1 + p] = ei1[e];
    } else if (e < E1 + E2) {
        int f = e - E1;
        int dst = ei2[E2 + f];
        int p = atomicAdd(&g_cnt2[dst], 1);
        if (p < CAP2) g_bkt2[(size_t)dst * CAP2 + p] = ei2[f];
    }
}

// ---------------- weight prep: g_wbT[n][k] bf16, concat+pad -----------------
__global__ void k_prep(const float* __restrict__ Wl1, const float* __restrict__ Wr1) {
    int idx = blockIdx.x * blockDim.x + threadIdx.x;   // k*256+n
    if (idx >= KTOT * HID) return;
    int k = idx >> 8, n = idx & 255;
    float v = 0.f;
    if (k < IN_C)                      v = Wl1[(size_t)k * HID + n];
    else if (k >= KP && k < KP + IN_C) v = Wr1[(size_t)(k - KP) * HID + n];
    g_wbT[(size_t)n * KTOT + k] = __float2bfloat16(v);
}

// ---------------- x_dst -> bf16 padded ----------------
__global__ void k_xcast(const float* __restrict__ x) {
    int idx = blockIdx.x * blockDim.x + threadIdx.x;   // word index, [N1*304]
    if (idx >= N1 * (KP / 2)) return;
    int row = idx / (KP / 2), w = idx % (KP / 2);
    int c = w * 2;
    float a = (c < IN_C)     ? x[(size_t)row * IN_C + c] : 0.f;
    float b = (c + 1 < IN_C) ? x[(size_t)row * IN_C + c + 1] : 0.f;
    g_xb[idx] = __floats2bfloat162_rn(a, b);
}

// ---------------- layer-1 mean aggregation -> bf16 padded -------------------
__global__ void __launch_bounds__(128) k_agg1(const float* __restrict__ x) {
    int dst = blockIdx.x;
    int t = threadIdx.x;                       // 128 threads
    int deg = g_cnt1[dst];
    int n = min(deg, CAP1);
    const int* bkt = &g_bkt1[(size_t)dst * CAP1];
    float2 acc0 = {0.f, 0.f}, acc1 = {0.f, 0.f}, acc2 = {0.f, 0.f};
    const float2* xb = reinterpret_cast<const float2*>(x);   // 301 float2/row
    int f2 = t + 256;
    int i = 0;
    for (; i + 1 < n; i += 2) {
        long long r0 = (long long)bkt[i] * 301;
        long long r1 = (long long)bkt[i + 1] * 301;
        float2 a = __ldg(&xb[r0 + t]);
        float2 b = __ldg(&xb[r0 + t + 128]);
        float2 c = (f2 < 301) ? __ldg(&xb[r0 + f2]) : make_float2(0.f, 0.f);
        float2 d = __ldg(&xb[r1 + t]);
        float2 g = __ldg(&xb[r1 + t + 128]);
        float2 h = (f2 < 301) ? __ldg(&xb[r1 + f2]) : make_float2(0.f, 0.f);
        acc0.x += a.x + d.x; acc0.y += a.y + d.y;
        acc1.x += b.x + g.x; acc1.y += b.y + g.y;
        acc2.x += c.x + h.x; acc2.y += c.y + h.y;
    }
    if (i < n) {
        long long r0 = (long long)bkt[i] * 301;
        float2 a = __ldg(&xb[r0 + t]);
        float2 b = __ldg(&xb[r0 + t + 128]);
        acc0.x += a.x; acc0.y += a.y;
        acc1.x += b.x; acc1.y += b.y;
        if (f2 < 301) { float2 c = __ldg(&xb[r0 + f2]); acc2.x += c.x; acc2.y += c.y; }
    }
    float inv = (deg > 0) ? 1.0f / (float)deg : 0.0f;
    __nv_bfloat162* ob = g_a1b + (long long)dst * (KP / 2);    // 304 words/row
    ob[t]       = __floats2bfloat162_rn(acc0.x * inv, acc0.y * inv);
    ob[t + 128] = __floats2bfloat162_rn(acc1.x * inv, acc1.y * inv);
    if (t < 48) {
        int w2 = t + 256;
        __nv_bfloat162 z = __floats2bfloat162_rn(
            (w2 < 301) ? acc2.x * inv : 0.f,
            (w2 < 301) ? acc2.y * inv : 0.f);
        ob[w2] = z;
    }
}

// ---------------- MMA / ldmatrix / cp.async helpers ----------------
__device__ __forceinline__ void mma_bf16(float& c0, float& c1, float& c2, float& c3,
                                         unsigned a0, unsigned a1, unsigned a2, unsigned a3,
                                         unsigned b0, unsigned b1) {
    asm volatile("mma.sync.aligned.m16n8k16.row.col.f32.bf16.bf16.f32 "
                 "{%0,%1,%2,%3}, {%4,%5,%6,%7}, {%8,%9}, {%0,%1,%2,%3};"
                 : "+f"(c0), "+f"(c1), "+f"(c2), "+f"(c3)
                 : "r"(a0), "r"(a1), "r"(a2), "r"(a3), "r"(b0), "r"(b1));
}
__device__ __forceinline__ void ldsm4(unsigned* r, unsigned addr) {
    asm volatile("ldmatrix.sync.aligned.m8n8.x4.shared.b16 {%0,%1,%2,%3}, [%4];"
                 : "=r"(r[0]), "=r"(r[1]), "=r"(r[2]), "=r"(r[3]) : "r"(addr));
}
__device__ __forceinline__ void cpa16(unsigned saddr, const void* g) {
    asm volatile("cp.async.cg.shared.global [%0], [%1], 16;" :: "r"(saddr), "l"(g));
}
__device__ __forceinline__ void cpa_commit() { asm volatile("cp.async.commit_group;"); }

// ---------------- fused GEMM1 (bf16 MMA, ldmatrix, 3-stage cp.async) --------
// h = relu([agg1 | x_dst] @ [Wl1;Wr1] + bl1)
// M=22528, K=1216 (padded), N=256. Block 128x64, 8 warps (4m x 2n), warp 32x32.
#define KSW 20
#define NSTG 3
__global__ void __launch_bounds__(256) k_gemm1(const float* __restrict__ bl1) {
    __shared__ __align__(16) unsigned As[NSTG][128 * KSW];   // 30720 B
    __shared__ __align__(16) unsigned Bs[NSTG][64 * KSW];    // 15360 B
    int tid = threadIdx.x;
    int bm = blockIdx.x * 128;
    int bn = blockIdx.y * 64;
    int warp = tid >> 5, lane = tid & 31;
    int wm = (warp & 3) * 32;
    int wn = (warp >> 2) * 32;
    int gid = lane >> 2, tig = lane & 3;

    // cp.async per-thread coords
    int ar = tid >> 1;                 // A row (2 chunks/thread)
    int ac = (tid & 1) * 2;            // first 16B chunk
    int br = tid >> 2;                 // B row (n)
    int bc = tid & 3;

    const __nv_bfloat16* a1p = reinterpret_cast<const __nv_bfloat16*>(g_a1b);
    const __nv_bfloat16* xbp = reinterpret_cast<const __nv_bfloat16*>(g_xb);

    float acc[2][4][4];
#pragma unroll
    for (int mt = 0; mt < 2; mt++)
#pragma unroll
        for (int nt = 0; nt < 4; nt++)
#pragma unroll
            for (int r = 0; r < 4; r++) acc[mt][nt][r] = 0.f;

    unsigned sA[NSTG], sB[NSTG];
#pragma unroll
    for (int s = 0; s < NSTG; s++) {
        sA[s] = (unsigned)__cvta_generic_to_shared(&As[s][0]);
        sB[s] = (unsigned)__cvta_generic_to_shared(&Bs[s][0]);
    }

    // ldmatrix lane address components
    int a_ro = (lane & 7) + ((lane >> 3) & 1) * 8;
    int a_kw = (lane >> 4) * 4;
    int aoffw[2];
#pragma unroll
    for (int mt = 0; mt < 2; mt++) aoffw[mt] = (wm + mt * 16 + a_ro) * KSW + a_kw;
    int b_ro = (lane & 7) + ((lane >> 4) << 3);
    int b_kw = ((lane >> 3) & 1) * 4;
    int boffw[2];
#pragma unroll
    for (int p = 0; p < 2; p++) boffw[p] = (wn + p * 16 + b_ro) * KSW + b_kw;

    auto load_tile = [&](int buf, int kt) {
        const __nv_bfloat16* src = (kt < 19) ? a1p : xbp;
        int k0 = ((kt < 19) ? kt : kt - 19) * 32;
#pragma unroll
        for (int i = 0; i < 2; i++) {
            int c = ac + i;
            const void* g = src + ((size_t)(bm + ar)) * KP + k0 + c * 8;
            cpa16(sA[buf] + (ar * KSW + c * 4) * 4, g);
        }
        {
            const void* g = g_wbT + ((size_t)(bn + br)) * KTOT + kt * 32 + bc * 8;
            cpa16(sB[buf] + (br * KSW + bc * 4) * 4, g);
        }
    };

    load_tile(0, 0); cpa_commit();
    load_tile(1, 1); cpa_commit();

    for (int kt = 0; kt < NKT; kt++) {
        int st = kt % NSTG;
        asm volatile("cp.async.wait_group 1;");
        __syncthreads();                       // stage kt visible to all
        if (kt + 2 < NKT) { load_tile((kt + 2) % NSTG, kt + 2); cpa_commit(); }

#pragma unroll
        for (int half = 0; half < 2; half++) {
            unsigned af[2][4], bf[2][4];
#pragma unroll
            for (int mt = 0; mt < 2; mt++)
                ldsm4(af[mt], sA[st] + (aoffw[mt] + half * 8) * 4);
#pragma unroll
            for (int p = 0; p < 2; p++)
                ldsm4(bf[p], sB[st] + (boffw[p] + half * 8) * 4);
#pragma unroll
            for (int mt = 0; mt < 2; mt++)
#pragma unroll
                for (int nt = 0; nt < 4; nt++) {
                    int p = nt >> 1, q = (nt & 1) * 2;
                    mma_bf16(acc[mt][nt][0], acc[mt][nt][1], acc[mt][nt][2], acc[mt][nt][3],
                             af[mt][0], af[mt][1], af[mt][2], af[mt][3],
                             bf[p][q], bf[p][q + 1]);
                }
        }
    }

    // epilogue: bias + relu
#pragma unroll
    for (int nt = 0; nt < 4; nt++) {
        int c = bn + wn + nt * 8 + tig * 2;
        float b0 = bl1[c], b1 = bl1[c + 1];
#pragma unroll
        for (int mt = 0; mt < 2; mt++) {
            int r0 = bm + wm + mt * 16 + gid;
            float2 o0, o1;
            o0.x = fmaxf(acc[mt][nt][0] + b0, 0.f);
            o0.y = fmaxf(acc[mt][nt][1] + b1, 0.f);
            o1.x = fmaxf(acc[mt][nt][2] + b0, 0.f);
            o1.y = fmaxf(acc[mt][nt][3] + b1, 0.f);
            *reinterpret_cast<float2*>(&g_h[(long long)r0 * 256 + c]) = o0;
            *reinterpret_cast<float2*>(&g_h[(long long)(r0 + 8) * 256 + c]) = o1;
        }
    }
}

// ---------------- layer-2 mean aggregation (256 feats, float4) --------------
__global__ void __launch_bounds__(64) k_agg2() {
    int dst = blockIdx.x;
    int t = threadIdx.x;
    int deg = g_cnt2[dst];
    int n = min(deg, CAP2);
    const int* bkt = &g_bkt2[(size_t)dst * CAP2];
    float4 acc = {0.f, 0.f, 0.f, 0.f};
    const float4* hb = reinterpret_cast<const float4*>(g_h);
    for (int i = 0; i < n; i++) {
        float4 v = __ldg(&hb[(long long)bkt[i] * 64 + t]);
        acc.x += v.x; acc.y += v.y; acc.z += v.z; acc.w += v.w;
    }
    float inv = (deg > 0) ? 1.0f / (float)deg : 0.0f;
    acc.x *= inv; acc.y *= inv; acc.z *= inv; acc.w *= inv;
    reinterpret_cast<float4*>(g_agg2)[(long long)dst * 64 + t] = acc;
}

// ---------------- GEMM2 + bias + log_softmax ----------------
__global__ void __launch_bounds__(64) k_out(const float* __restrict__ Wl2,
                                            const float* __restrict__ bl2,
                                            const float* __restrict__ Wr2,
                                            float* __restrict__ out) {
    __shared__ __align__(16) float sA[HID];
    __shared__ __align__(16) float sH[HID];
    __shared__ float sO[OUT_C];
    __shared__ float s_mx, s_ls;
    int row = blockIdx.x, t = threadIdx.x;
    reinterpret_cast<float4*>(sA)[t] = reinterpret_cast<const float4*>(g_agg2)[(long long)row * 64 + t];
    reinterpret_cast<float4*>(sH)[t] = reinterpret_cast<const float4*>(g_h)[(long long)row * 64 + t];
    __syncthreads();
    if (t < OUT_C) {
        float acc = bl2[t];
#pragma unroll 8
        for (int k = 0; k < HID; k++)
            acc += sA[k] * __ldg(&Wl2[k * OUT_C + t]) + sH[k] * __ldg(&Wr2[k * OUT_C + t]);
        sO[t] = acc;
    }
    __syncthreads();
    if (t == 0) {
        float mx = -1e30f;
        for (int j = 0; j < OUT_C; j++) mx = fmaxf(mx, sO[j]);
        float se = 0.f;
        for (int j = 0; j < OUT_C; j++) se += expf(sO[j] - mx);
        s_mx = mx; s_ls = logf(se);
    }
    __syncthreads();
    if (t < OUT_C) out[(long long)row * OUT_C + t] = sO[t] - s_mx - s_ls;
}

// ---------------- launch ----------------
extern "C" void kernel_launch(void* const* d_in, const int* in_sizes, int n_in,
                              void* d_out, int out_size) {
    const float* x   = (const float*)d_in[0];
    const int*   ei1 = (const int*)d_in[1];     // int32 [2, E1]
    const int*   ei2 = (const int*)d_in[2];     // int32 [2, E2]
    const float* Wl1 = (const float*)d_in[3];
    const float* bl1 = (const float*)d_in[4];
    const float* Wr1 = (const float*)d_in[5];
    const float* Wl2 = (const float*)d_in[6];
    const float* bl2 = (const float*)d_in[7];
    const float* Wr2 = (const float*)d_in[8];
    float* out = (float*)d_out;

    // lazy one-time host resources (no device memory involved)
    static cudaStream_t s1 = nullptr;
    static cudaEvent_t evF = nullptr, evJ = nullptr;
    if (s1 == nullptr) {
        cudaStreamCreateWithFlags(&s1, cudaStreamNonBlocking);
        cudaEventCreateWithFlags(&evF, cudaEventDisableTiming);
        cudaEventCreateWithFlags(&evJ, cudaEventDisableTiming);
    }

    // fork: weight/x conversion on side stream
    cudaEventRecord(evF, 0);
    cudaStreamWaitEvent(s1, evF, 0);
    k_prep<<<(KTOT * HID + 255) / 256, 256, 0, s1>>>(Wl1, Wr1);
    k_xcast<<<(N1 * (KP / 2) + 255) / 256, 256, 0, s1>>>(x);
    cudaEventRecord(evJ, s1);

    // main chain: bucket build -> aggregation
    k_zero_cnt<<<(N1 + 255) / 256, 256>>>();
    k_fill_all<<<(E1 + E2 + 255) / 256, 256>>>(ei1, ei2);
    k_agg1<<<N1, 128>>>(x);

    // join, then GEMM + layer 2
    cudaStreamWaitEvent(0, evJ, 0);
    k_gemm1<<<dim3(176, 4), 256>>>(bl1);
    k_agg2<<<N2, 64>>>();
    k_out<<<N2, 64>>>(Wl2, bl2, Wr2, out);
}